// round 13
// baseline (speedup 1.0000x reference)
#include <cuda_runtime.h>
#include <math.h>
#include <stdint.h>

#define Bn 4
#define Sn 2048
#define Dn 1024
#define Hn 16
#define DKn 64
#define Mn (Bn*Sn)   /* 8192 */
#define LD 68        /* flash smem row stride for Q tile */
#define QT 128       /* q-tile rows per CTA in flash attention */

// Scratch (device globals: allocation-free per harness rules)
// g_Q: [b][h][s][d], tf32-rounded AND pre-scaled by 1/sqrt(DK)
// g_K: [b][h][d][s]  (TRANSPOSED), tf32-rounded
// g_V: [b][h][s][d], tf32-rounded
__device__ float g_Q[Bn*Hn*Sn*DKn];
__device__ float g_K[Bn*Hn*Sn*DKn];
__device__ float g_V[Bn*Hn*Sn*DKn];
__device__ float g_ctx[Mn*Dn];

__device__ __forceinline__ uint32_t f2tf(float f) {
    uint32_t u;
    asm("cvt.rna.tf32.f32 %0, %1;" : "=r"(u) : "f"(f));
    return u;
}
__device__ __forceinline__ float tf32r(float f) { return __uint_as_float(f2tf(f)); }

#define MMA_TF32(c, a, b) asm volatile( \
    "mma.sync.aligned.m16n8k8.row.col.f32.tf32.tf32.f32 " \
    "{%0,%1,%2,%3}, {%4,%5,%6,%7}, {%8,%9}, {%0,%1,%2,%3};\n" \
    : "+f"((c)[0]), "+f"((c)[1]), "+f"((c)[2]), "+f"((c)[3]) \
    : "r"((a)[0]), "r"((a)[1]), "r"((a)[2]), "r"((a)[3]), \
      "r"((b)[0]), "r"((b)[1]))

// ---------------------------------------------------------------------------
// tf32 tensor-core GEMM core (R8/R11-proven): double-buffered, XOR-swizzled
// fragment smem. Computes C fragments for a 128x128 tile of A @ W.
// ---------------------------------------------------------------------------
__device__ __forceinline__ void storeAfrag(uint32_t* sA, int arow, int k4, float4 v) {
    const int kt  = k4 >> 3;
    const int reg = (((arow & 15) >= 8) ? 1 : 0) | ((k4 & 4) ? 2 : 0);
    const int a7  = arow & 7;
    const int swz = ((a7 >> 1) & 3) << 2;
    const int base = (((arow >> 4) * 2 + kt) << 7) + (a7 << 4) + reg;
    sA[(base + 0)  ^ swz] = f2tf(v.x);
    sA[(base + 4)  ^ swz] = f2tf(v.y);
    sA[(base + 8)  ^ swz] = f2tf(v.z);
    sA[(base + 12) ^ swz] = f2tf(v.w);
}

__device__ __forceinline__ void storeBfrag(uint32_t* sB, int krow, int n4, float4 v) {
    const int kt    = krow >> 3;
    const int reg   = ((krow & 7) >= 4) ? 1 : 0;
    const int ntile = (n4 >> 3) * 2 + kt;
    const int swz   = ((ntile & 3) << 1) | (((ntile >> 2) & 3) << 3);
    const int base  = ntile * 64 + (n4 & 7) * 8 + (krow & 3) * 2 + reg;
    sB[(base + 0)  ^ swz] = f2tf(v.x);
    sB[(base + 8)  ^ swz] = f2tf(v.y);
    sB[(base + 16) ^ swz] = f2tf(v.z);
    sB[(base + 24) ^ swz] = f2tf(v.w);
}

__device__ __forceinline__ void gemm_body(
    const float* __restrict__ A, const float* __restrict__ W,
    float c[2][8][4], uint32_t (*sA)[2048], uint32_t (*sB)[2048],
    int bx, int by)
{
    const int tid  = threadIdx.x;
    const int wid  = tid >> 5;
    const int lane = tid & 31;
    const int wm   = wid & 3;
    const int wn   = wid >> 2;
    const int la   = (lane << 2) ^ (((lane >> 3) & 3) << 2);

    #pragma unroll
    for (int mt = 0; mt < 2; mt++)
        #pragma unroll
        for (int nt = 0; nt < 8; nt++)
            #pragma unroll
            for (int r = 0; r < 4; r++) c[mt][nt][r] = 0.f;

    const int arow  = tid >> 1;
    const int acol8 = (tid & 1) * 8;
    const int brow  = tid >> 4;
    const int bcol8 = (tid & 15) * 8;

    const float* Ap = A + (size_t)(by * 128 + arow) * Dn + acol8;
    const float* Wp = W + (size_t)brow * Dn + bx * 128 + bcol8;

    float4 ar0 = *(const float4*)Ap;
    float4 ar1 = *(const float4*)(Ap + 4);
    float4 wr0 = *(const float4*)Wp;
    float4 wr1 = *(const float4*)(Wp + 4);
    Ap += 16; Wp += (size_t)16 * Dn;

    storeAfrag(sA[0], arow, acol8,     ar0);
    storeAfrag(sA[0], arow, acol8 + 4, ar1);
    storeBfrag(sB[0], brow, bcol8,     wr0);
    storeBfrag(sB[0], brow, bcol8 + 4, wr1);
    __syncthreads();

    const int NIT = Dn / 16;
    for (int it = 0; it < NIT; it++) {
        const int  p    = it & 1;
        const bool more = (it + 1 < NIT);
        if (more) {
            ar0 = *(const float4*)Ap;
            ar1 = *(const float4*)(Ap + 4);
            wr0 = *(const float4*)Wp;
            wr1 = *(const float4*)(Wp + 4);
            Ap += 16; Wp += (size_t)16 * Dn;
        }

        #pragma unroll
        for (int kt = 0; kt < 2; kt++) {
            uint32_t af[2][4];
            uint32_t bf[8][2];
            #pragma unroll
            for (int mt = 0; mt < 2; mt++)
                *(uint4*)af[mt] =
                    *(const uint4*)&sA[p][(((wm * 2 + mt) * 2 + kt) << 7) + la];
            #pragma unroll
            for (int nt = 0; nt < 8; nt++) {
                const int ntile = (wn * 8 + nt) * 2 + kt;
                const int swz   = ((ntile & 3) << 1) | (((ntile >> 2) & 3) << 3);
                *(uint2*)bf[nt] =
                    *(const uint2*)&sB[p][ntile * 64 + ((lane << 1) ^ swz)];
            }
            #pragma unroll
            for (int mt = 0; mt < 2; mt++)
                #pragma unroll
                for (int nt = 0; nt < 8; nt++)
                    MMA_TF32(c[mt][nt], af[mt], bf[nt]);
        }

        if (more) {
            storeAfrag(sA[p ^ 1], arow, acol8,     ar0);
            storeAfrag(sA[p ^ 1], arow, acol8 + 4, ar1);
            storeBfrag(sB[p ^ 1], brow, bcol8,     wr0);
            storeBfrag(sB[p ^ 1], brow, bcol8 + 4, wr1);
            __syncthreads();
        }
    }
}

// ---------------------------------------------------------------------------
// Fused Q/K/V projection GEMMs (grid.z selects). Epilogues write the layouts
// flash consumes directly: Q split+scaled+tf32, K TRANSPOSED [d][s]+tf32,
// V split+tf32.
// ---------------------------------------------------------------------------
__global__ __launch_bounds__(256) void gemm_qkv(
    const float* __restrict__ q, const float* __restrict__ k,
    const float* __restrict__ v,
    const float* __restrict__ Wq, const float* __restrict__ Wk,
    const float* __restrict__ Wv,
    const float* __restrict__ bq, const float* __restrict__ bk,
    const float* __restrict__ bv)
{
    __shared__ uint32_t sA[2][2048];
    __shared__ uint32_t sB[2][2048];

    const int dst = blockIdx.z;
    const float* A    = (dst == 0) ? q  : (dst == 1) ? k  : v;
    const float* W    = (dst == 0) ? Wq : (dst == 1) ? Wk : Wv;
    const float* bias = (dst == 0) ? bq : (dst == 1) ? bk : bv;
    const float  scl  = (dst == 0) ? 0.125f : 1.0f;

    float c[2][8][4];
    gemm_body(A, W, c, sA, sB, blockIdx.x, blockIdx.y);

    const int lane = threadIdx.x & 31;
    const int wid  = threadIdx.x >> 5;
    const int wm   = wid & 3;
    const int wn   = wid >> 2;
    const int gid  = lane >> 2;
    const int tig  = lane & 3;

    #pragma unroll
    for (int mt = 0; mt < 2; mt++) {
        const int m0 = blockIdx.y * 128 + wm * 32 + mt * 16 + gid;
        const int m1 = m0 + 8;
        const int b0i = m0 >> 11, s0 = m0 & (Sn - 1);
        const int b1i = m1 >> 11, s1 = m1 & (Sn - 1);
        #pragma unroll
        for (int nt = 0; nt < 8; nt++) {
            const int n = blockIdx.x * 128 + wn * 64 + nt * 8 + tig * 2;
            const int h  = n >> 6;
            const int dk = n & 63;
            const float r0 = tf32r((c[mt][nt][0] + bias[n])     * scl);
            const float r1 = tf32r((c[mt][nt][1] + bias[n + 1]) * scl);
            const float r2 = tf32r((c[mt][nt][2] + bias[n])     * scl);
            const float r3 = tf32r((c[mt][nt][3] + bias[n + 1]) * scl);
            if (dst == 1) {
                // K transposed: [b][h][d][s]
                float* K0 = g_K + ((size_t)(b0i * Hn + h) * DKn + dk) * Sn;
                K0[s0]       = r0;
                K0[Sn + s0]  = r1;       // dk+1 row
                float* K1 = g_K + ((size_t)(b1i * Hn + h) * DKn + dk) * Sn;
                K1[s1]       = r2;
                K1[Sn + s1]  = r3;
            } else {
                float* Out = (dst == 0) ? g_Q : g_V;
                float2 v0 = { r0, r1 };
                float2 v1 = { r2, r3 };
                *(float2*)&Out[((size_t)(b0i * Hn + h) * Sn + s0) * DKn + dk] = v0;
                *(float2*)&Out[((size_t)(b1i * Hn + h) * Sn + s1) * DKn + dk] = v1;
            }
        }
    }
}

// Output projection: out = g_ctx @ Wo + bo (plain fp32 epilogue)
__global__ __launch_bounds__(256) void gemm_out(
    const float* __restrict__ Wo, const float* __restrict__ bo,
    float* __restrict__ out)
{
    __shared__ uint32_t sA[2][2048];
    __shared__ uint32_t sB[2][2048];

    float c[2][8][4];
    gemm_body((const float*)g_ctx, Wo, c, sA, sB, blockIdx.x, blockIdx.y);

    const int lane = threadIdx.x & 31;
    const int wid  = threadIdx.x >> 5;
    const int wm   = wid & 3;
    const int wn   = wid >> 2;
    const int gid  = lane >> 2;
    const int tig  = lane & 3;

    #pragma unroll
    for (int mt = 0; mt < 2; mt++) {
        const int m0 = blockIdx.y * 128 + wm * 32 + mt * 16 + gid;
        #pragma unroll
        for (int nt = 0; nt < 8; nt++) {
            const int n = blockIdx.x * 128 + wn * 64 + nt * 8 + tig * 2;
            float2 v0 = { c[mt][nt][0] + bo[n], c[mt][nt][1] + bo[n + 1] };
            float2 v1 = { c[mt][nt][2] + bo[n], c[mt][nt][3] + bo[n + 1] };
            *(float2*)&out[(size_t)m0 * Dn + n]       = v0;
            *(float2*)&out[(size_t)(m0 + 8) * Dn + n] = v1;
        }
    }
}

// ---------------------------------------------------------------------------
// FA2-style flash attention, gmem-direct K/V fragments (no K/V smem staging,
// no per-tile barriers). Q tile in smem; additive mask precomputed in smem.
// S/P in registers; in-register online softmax; P->A-frag via shuffles.
// ---------------------------------------------------------------------------
__global__ __launch_bounds__(256, 2) void flash_attn(const int* __restrict__ mask)
{
    __shared__ float Qs[QT * LD];      // 34816 B
    __shared__ float mskf[Sn];         //  8192 B  (0 or -1e30 per key)

    const int tid = threadIdx.x;
    const int qt  = blockIdx.x;
    const int h   = blockIdx.y;
    const int b   = blockIdx.z;
    const int q0  = qt * QT;

    const int lane = tid & 31;
    const int gid  = lane >> 2;
    const int tig  = lane & 3;
    const int row0 = (tid >> 5) * 16 + gid;

    const float* Qg  = g_Q + ((size_t)(b * Hn + h) * Sn + q0) * DKn;
    const float* KTg = g_K + (size_t)(b * Hn + h) * DKn * Sn;   // [d][s]
    const float* Vg  = g_V + (size_t)(b * Hn + h) * Sn * DKn;   // [s][d]

    // Q tile raw copy (already tf32 + scaled); mask row -> additive floats
    {
        const int r   = tid >> 1;
        const int c32 = (tid & 1) * 32;
        #pragma unroll
        for (int u = 0; u < 32; u += 4)
            *(float4*)&Qs[r * LD + c32 + u] = *(const float4*)&Qg[r * DKn + c32 + u];
        #pragma unroll
        for (int i = 0; i < Sn / 256; i++)
            mskf[tid + i * 256] = (mask[b * Sn + tid + i * 256] == 0) ? -1e30f : 0.f;
    }
    __syncthreads();

    float m0 = -1e30f, m1 = -1e30f, l0 = 0.f, l1 = 0.f;
    float o[8][4];
    #pragma unroll
    for (int nt = 0; nt < 8; nt++)
        #pragma unroll
        for (int r = 0; r < 4; r++) o[nt][r] = 0.f;

    for (int kt = 0; kt < Sn / 64; kt++) {
        const int kk0 = kt * 64;

        // S = Q @ K^T : K fragments straight from gmem (transposed layout)
        float s[8][4];
        #pragma unroll
        for (int nt = 0; nt < 8; nt++)
            #pragma unroll
            for (int r = 0; r < 4; r++) s[nt][r] = 0.f;

        #pragma unroll
        for (int ks = 0; ks < 8; ks++) {
            const int kk = ks * 8;
            uint32_t a[4];
            const float* Ap = &Qs[row0 * LD + kk + tig];
            a[0] = __float_as_uint(Ap[0]);
            a[1] = __float_as_uint(Ap[8 * LD]);
            a[2] = __float_as_uint(Ap[4]);
            a[3] = __float_as_uint(Ap[8 * LD + 4]);
            const float* Kr0 = KTg + (size_t)(kk + tig) * Sn + kk0 + gid;
            const float* Kr1 = Kr0 + (size_t)4 * Sn;
            #pragma unroll
            for (int nt = 0; nt < 8; nt++) {
                uint32_t bb[2];
                bb[0] = __float_as_uint(Kr0[nt * 8]);
                bb[1] = __float_as_uint(Kr1[nt * 8]);
                MMA_TF32(s[nt], a, bb);
            }
        }

        // Additive mask (0 or -1e30; -1e30+s rounds to exactly -1e30)
        float mx0 = -1e30f, mx1 = -1e30f;
        #pragma unroll
        for (int nt = 0; nt < 8; nt++) {
            const float2 mv = *(const float2*)&mskf[kk0 + nt * 8 + tig * 2];
            s[nt][0] += mv.x; s[nt][1] += mv.y;
            s[nt][2] += mv.x; s[nt][3] += mv.y;
            mx0 = fmaxf(mx0, fmaxf(s[nt][0], s[nt][1]));
            mx1 = fmaxf(mx1, fmaxf(s[nt][2], s[nt][3]));
        }
        mx0 = fmaxf(mx0, __shfl_xor_sync(0xffffffffu, mx0, 1));
        mx0 = fmaxf(mx0, __shfl_xor_sync(0xffffffffu, mx0, 2));
        mx1 = fmaxf(mx1, __shfl_xor_sync(0xffffffffu, mx1, 1));
        mx1 = fmaxf(mx1, __shfl_xor_sync(0xffffffffu, mx1, 2));

        const float mn0 = fmaxf(m0, mx0);
        const float mn1 = fmaxf(m1, mx1);
        const float f0  = __expf(m0 - mn0);
        const float f1  = __expf(m1 - mn1);
        m0 = mn0; m1 = mn1;

        float sum0 = 0.f, sum1 = 0.f;
        #pragma unroll
        for (int nt = 0; nt < 8; nt++) {
            float p0 = (s[nt][0] <= -1e29f) ? 0.f : tf32r(__expf(s[nt][0] - mn0));
            float p1 = (s[nt][1] <= -1e29f) ? 0.f : tf32r(__expf(s[nt][1] - mn0));
            float p2 = (s[nt][2] <= -1e29f) ? 0.f : tf32r(__expf(s[nt][2] - mn1));
            float p3 = (s[nt][3] <= -1e29f) ? 0.f : tf32r(__expf(s[nt][3] - mn1));
            s[nt][0] = p0; s[nt][1] = p1; s[nt][2] = p2; s[nt][3] = p3;
            sum0 += p0 + p1;
            sum1 += p2 + p3;
        }
        sum0 += __shfl_xor_sync(0xffffffffu, sum0, 1);
        sum0 += __shfl_xor_sync(0xffffffffu, sum0, 2);
        sum1 += __shfl_xor_sync(0xffffffffu, sum1, 1);
        sum1 += __shfl_xor_sync(0xffffffffu, sum1, 2);
        l0 = l0 * f0 + sum0;
        l1 = l1 * f1 + sum1;

        // Rescale O
        #pragma unroll
        for (int nt = 0; nt < 8; nt++) {
            o[nt][0] *= f0; o[nt][1] *= f0;
            o[nt][2] *= f1; o[nt][3] *= f1;
        }

        // O += P @ V : V fragments straight from gmem (row-major layout)
        {
            const int srcA = (lane & ~3) | (tig >> 1);
            const int srcB = srcA + 2;
            const bool odd = (tig & 1) != 0;
            #pragma unroll
            for (int ks = 0; ks < 8; ks++) {
                const float v00 = __shfl_sync(0xffffffffu, s[ks][0], srcA);
                const float v01 = __shfl_sync(0xffffffffu, s[ks][1], srcA);
                const float v02 = __shfl_sync(0xffffffffu, s[ks][2], srcA);
                const float v03 = __shfl_sync(0xffffffffu, s[ks][3], srcA);
                const float v10 = __shfl_sync(0xffffffffu, s[ks][0], srcB);
                const float v11 = __shfl_sync(0xffffffffu, s[ks][1], srcB);
                const float v12 = __shfl_sync(0xffffffffu, s[ks][2], srcB);
                const float v13 = __shfl_sync(0xffffffffu, s[ks][3], srcB);
                uint32_t a[4];
                a[0] = __float_as_uint(odd ? v01 : v00);
                a[1] = __float_as_uint(odd ? v03 : v02);
                a[2] = __float_as_uint(odd ? v11 : v10);
                a[3] = __float_as_uint(odd ? v13 : v12);

                const int kk = ks * 8;
                const float* Vr0 = Vg + (size_t)(kk0 + kk + tig) * DKn + gid;
                const float* Vr1 = Vr0 + (size_t)4 * DKn;
                #pragma unroll
                for (int nt = 0; nt < 8; nt++) {
                    uint32_t bb[2];
                    bb[0] = __float_as_uint(Vr0[nt * 8]);
                    bb[1] = __float_as_uint(Vr1[nt * 8]);
                    MMA_TF32(o[nt], a, bb);
                }
            }
        }
        // no barrier — warps free-run across k-tiles
    }

    // Normalize and write ctx in (B,S,D) layout
    {
        const float inv0 = 1.f / l0;
        const float inv1 = 1.f / l1;
        #pragma unroll
        for (int nt = 0; nt < 8; nt++) {
            const int col = h * DKn + nt * 8 + tig * 2;
            float2 v0 = { o[nt][0] * inv0, o[nt][1] * inv0 };
            float2 v1 = { o[nt][2] * inv1, o[nt][3] * inv1 };
            *(float2*)&g_ctx[(size_t)(b * Sn + q0 + row0) * Dn + col]     = v0;
            *(float2*)&g_ctx[(size_t)(b * Sn + q0 + row0 + 8) * Dn + col] = v1;
        }
    }
}

// ---------------------------------------------------------------------------
extern "C" void kernel_launch(void* const* d_in, const int* in_sizes, int n_in,
                              void* d_out, int out_size)
{
    const float* q    = (const float*)d_in[0];
    const float* k    = (const float*)d_in[1];
    const float* v    = (const float*)d_in[2];
    const int*   mask = (const int*)  d_in[3];
    const float* Wq   = (const float*)d_in[4];
    const float* bq   = (const float*)d_in[5];
    const float* Wk   = (const float*)d_in[6];
    const float* bk   = (const float*)d_in[7];
    const float* Wv   = (const float*)d_in[8];
    const float* bv   = (const float*)d_in[9];
    const float* Wo   = (const float*)d_in[10];
    const float* bo   = (const float*)d_in[11];
    float* out = (float*)d_out;

    const dim3 gq(Dn / 128, Mn / 128, 3);
    gemm_qkv<<<gq, 256>>>(q, k, v, Wq, Wk, Wv, bq, bk, bv);

    const dim3 ga(Sn / QT, Hn, Bn);
    flash_attn<<<ga, 256>>>(mask);

    const dim3 gg(Dn / 128, Mn / 128);
    gemm_out<<<gg, 256>>>(Wo, bo, out);
}

// round 15
// speedup vs baseline: 1.1747x; 1.1747x over previous
#include <cuda_runtime.h>
#include <math.h>
#include <stdint.h>

#define Bn 4
#define Sn 2048
#define Dn 1024
#define Hn 16
#define DKn 64
#define Mn (Bn*Sn)   /* 8192 */
#define LD 68        /* flash smem row stride: Q/K tiles */
#define LDV 72       /* flash smem row stride: V tile */
#define QT 128       /* q-tile rows per CTA */
#define KT2 128      /* keys staged per smem tile (2 compute halves of 64) */

// Scratch (device globals: allocation-free per harness rules)
// g_Q: [b][h][s][d] tf32-rounded, pre-scaled by 1/sqrt(DK); g_K/g_V: tf32.
__device__ float g_Q[Bn*Hn*Sn*DKn];
__device__ float g_K[Bn*Hn*Sn*DKn];
__device__ float g_V[Bn*Hn*Sn*DKn];
__device__ float g_ctx[Mn*Dn];

__device__ __forceinline__ uint32_t f2tf(float f) {
    uint32_t u;
    asm("cvt.rna.tf32.f32 %0, %1;" : "=r"(u) : "f"(f));
    return u;
}
__device__ __forceinline__ float tf32r(float f) { return __uint_as_float(f2tf(f)); }

#define MMA_TF32(c, a, b) asm volatile( \
    "mma.sync.aligned.m16n8k8.row.col.f32.tf32.tf32.f32 " \
    "{%0,%1,%2,%3}, {%4,%5,%6,%7}, {%8,%9}, {%0,%1,%2,%3};\n" \
    : "+f"((c)[0]), "+f"((c)[1]), "+f"((c)[2]), "+f"((c)[3]) \
    : "r"((a)[0]), "r"((a)[1]), "r"((a)[2]), "r"((a)[3]), \
      "r"((b)[0]), "r"((b)[1]))

// ---------------------------------------------------------------------------
// tf32 tensor-core GEMM core (R8/R11-proven): double-buffered, XOR-swizzled
// fragment smem. Computes C fragments for a 128x128 tile of A @ W.
// ---------------------------------------------------------------------------
__device__ __forceinline__ void storeAfrag(uint32_t* sA, int arow, int k4, float4 v) {
    const int kt  = k4 >> 3;
    const int reg = (((arow & 15) >= 8) ? 1 : 0) | ((k4 & 4) ? 2 : 0);
    const int a7  = arow & 7;
    const int swz = ((a7 >> 1) & 3) << 2;
    const int base = (((arow >> 4) * 2 + kt) << 7) + (a7 << 4) + reg;
    sA[(base + 0)  ^ swz] = f2tf(v.x);
    sA[(base + 4)  ^ swz] = f2tf(v.y);
    sA[(base + 8)  ^ swz] = f2tf(v.z);
    sA[(base + 12) ^ swz] = f2tf(v.w);
}

__device__ __forceinline__ void storeBfrag(uint32_t* sB, int krow, int n4, float4 v) {
    const int kt    = krow >> 3;
    const int reg   = ((krow & 7) >= 4) ? 1 : 0;
    const int ntile = (n4 >> 3) * 2 + kt;
    const int swz   = ((ntile & 3) << 1) | (((ntile >> 2) & 3) << 3);
    const int base  = ntile * 64 + (n4 & 7) * 8 + (krow & 3) * 2 + reg;
    sB[(base + 0)  ^ swz] = f2tf(v.x);
    sB[(base + 8)  ^ swz] = f2tf(v.y);
    sB[(base + 16) ^ swz] = f2tf(v.z);
    sB[(base + 24) ^ swz] = f2tf(v.w);
}

__device__ __forceinline__ void gemm_body(
    const float* __restrict__ A, const float* __restrict__ W,
    float c[2][8][4], uint32_t (*sA)[2048], uint32_t (*sB)[2048],
    int bx, int by)
{
    const int tid  = threadIdx.x;
    const int wid  = tid >> 5;
    const int lane = tid & 31;
    const int wm   = wid & 3;
    const int wn   = wid >> 2;
    const int la   = (lane << 2) ^ (((lane >> 3) & 3) << 2);

    #pragma unroll
    for (int mt = 0; mt < 2; mt++)
        #pragma unroll
        for (int nt = 0; nt < 8; nt++)
            #pragma unroll
            for (int r = 0; r < 4; r++) c[mt][nt][r] = 0.f;

    const int arow  = tid >> 1;
    const int acol8 = (tid & 1) * 8;
    const int brow  = tid >> 4;
    const int bcol8 = (tid & 15) * 8;

    const float* Ap = A + (size_t)(by * 128 + arow) * Dn + acol8;
    const float* Wp = W + (size_t)brow * Dn + bx * 128 + bcol8;

    float4 ar0 = *(const float4*)Ap;
    float4 ar1 = *(const float4*)(Ap + 4);
    float4 wr0 = *(const float4*)Wp;
    float4 wr1 = *(const float4*)(Wp + 4);
    Ap += 16; Wp += (size_t)16 * Dn;

    storeAfrag(sA[0], arow, acol8,     ar0);
    storeAfrag(sA[0], arow, acol8 + 4, ar1);
    storeBfrag(sB[0], brow, bcol8,     wr0);
    storeBfrag(sB[0], brow, bcol8 + 4, wr1);
    __syncthreads();

    const int NIT = Dn / 16;
    for (int it = 0; it < NIT; it++) {
        const int  p    = it & 1;
        const bool more = (it + 1 < NIT);
        if (more) {
            ar0 = *(const float4*)Ap;
            ar1 = *(const float4*)(Ap + 4);
            wr0 = *(const float4*)Wp;
            wr1 = *(const float4*)(Wp + 4);
            Ap += 16; Wp += (size_t)16 * Dn;
        }

        #pragma unroll
        for (int kt = 0; kt < 2; kt++) {
            uint32_t af[2][4];
            uint32_t bf[8][2];
            #pragma unroll
            for (int mt = 0; mt < 2; mt++)
                *(uint4*)af[mt] =
                    *(const uint4*)&sA[p][(((wm * 2 + mt) * 2 + kt) << 7) + la];
            #pragma unroll
            for (int nt = 0; nt < 8; nt++) {
                const int ntile = (wn * 8 + nt) * 2 + kt;
                const int swz   = ((ntile & 3) << 1) | (((ntile >> 2) & 3) << 3);
                *(uint2*)bf[nt] =
                    *(const uint2*)&sB[p][ntile * 64 + ((lane << 1) ^ swz)];
            }
            #pragma unroll
            for (int mt = 0; mt < 2; mt++)
                #pragma unroll
                for (int nt = 0; nt < 8; nt++)
                    MMA_TF32(c[mt][nt], af[mt], bf[nt]);
        }

        if (more) {
            storeAfrag(sA[p ^ 1], arow, acol8,     ar0);
            storeAfrag(sA[p ^ 1], arow, acol8 + 4, ar1);
            storeBfrag(sB[p ^ 1], brow, bcol8,     wr0);
            storeBfrag(sB[p ^ 1], brow, bcol8 + 4, wr1);
            __syncthreads();
        }
    }
}

// ---------------------------------------------------------------------------
// Fused Q/K/V projection GEMMs (grid.z selects). All three write head-split
// row-major [b][h][s][d], tf32-rounded; Q additionally pre-scaled by 0.125.
// ---------------------------------------------------------------------------
__global__ __launch_bounds__(256) void gemm_qkv(
    const float* __restrict__ q, const float* __restrict__ k,
    const float* __restrict__ v,
    const float* __restrict__ Wq, const float* __restrict__ Wk,
    const float* __restrict__ Wv,
    const float* __restrict__ bq, const float* __restrict__ bk,
    const float* __restrict__ bv)
{
    __shared__ uint32_t sA[2][2048];
    __shared__ uint32_t sB[2][2048];

    const int dst = blockIdx.z;
    const float* A    = (dst == 0) ? q  : (dst == 1) ? k  : v;
    const float* W    = (dst == 0) ? Wq : (dst == 1) ? Wk : Wv;
    const float* bias = (dst == 0) ? bq : (dst == 1) ? bk : bv;
    float* Out        = (dst == 0) ? g_Q : (dst == 1) ? g_K : g_V;
    const float scl   = (dst == 0) ? 0.125f : 1.0f;

    float c[2][8][4];
    gemm_body(A, W, c, sA, sB, blockIdx.x, blockIdx.y);

    const int lane = threadIdx.x & 31;
    const int wid  = threadIdx.x >> 5;
    const int wm   = wid & 3;
    const int wn   = wid >> 2;
    const int gid  = lane >> 2;
    const int tig  = lane & 3;

    #pragma unroll
    for (int mt = 0; mt < 2; mt++) {
        const int m0 = blockIdx.y * 128 + wm * 32 + mt * 16 + gid;
        const int m1 = m0 + 8;
        const int b0i = m0 >> 11, s0 = m0 & (Sn - 1);
        const int b1i = m1 >> 11, s1 = m1 & (Sn - 1);
        #pragma unroll
        for (int nt = 0; nt < 8; nt++) {
            const int n = blockIdx.x * 128 + wn * 64 + nt * 8 + tig * 2;
            const int h  = n >> 6;
            const int dk = n & 63;
            float2 v0 = { tf32r((c[mt][nt][0] + bias[n])     * scl),
                          tf32r((c[mt][nt][1] + bias[n + 1]) * scl) };
            float2 v1 = { tf32r((c[mt][nt][2] + bias[n])     * scl),
                          tf32r((c[mt][nt][3] + bias[n + 1]) * scl) };
            *(float2*)&Out[((size_t)(b0i * Hn + h) * Sn + s0) * DKn + dk] = v0;
            *(float2*)&Out[((size_t)(b1i * Hn + h) * Sn + s1) * DKn + dk] = v1;
        }
    }
}

// Output projection: out = g_ctx @ Wo + bo (plain fp32 epilogue)
__global__ __launch_bounds__(256) void gemm_out(
    const float* __restrict__ Wo, const float* __restrict__ bo,
    float* __restrict__ out)
{
    __shared__ uint32_t sA[2][2048];
    __shared__ uint32_t sB[2][2048];

    float c[2][8][4];
    gemm_body((const float*)g_ctx, Wo, c, sA, sB, blockIdx.x, blockIdx.y);

    const int lane = threadIdx.x & 31;
    const int wid  = threadIdx.x >> 5;
    const int wm   = wid & 3;
    const int wn   = wid >> 2;
    const int gid  = lane >> 2;
    const int tig  = lane & 3;

    #pragma unroll
    for (int mt = 0; mt < 2; mt++) {
        const int m0 = blockIdx.y * 128 + wm * 32 + mt * 16 + gid;
        #pragma unroll
        for (int nt = 0; nt < 8; nt++) {
            const int n = blockIdx.x * 128 + wn * 64 + nt * 8 + tig * 2;
            float2 v0 = { c[mt][nt][0] + bo[n], c[mt][nt][1] + bo[n + 1] };
            float2 v1 = { c[mt][nt][2] + bo[n], c[mt][nt][3] + bo[n + 1] };
            *(float2*)&out[(size_t)m0 * Dn + n]       = v0;
            *(float2*)&out[(size_t)(m0 + 8) * Dn + n] = v1;
        }
    }
}

// ---------------------------------------------------------------------------
// FA2-style flash attention (R11-proven core): smem-staged K/V, register-
// resident S/P, in-register online softmax, P->A-frag via shuffles.
// R14 changes: 128-key staged tiles (2 compute halves -> half the barriers,
// 2x staging MLP) and additive mask (R13-verified bit-identical).
// ---------------------------------------------------------------------------
__global__ __launch_bounds__(256, 2) void flash_attn(const int* __restrict__ mask)
{
    extern __shared__ float sm[];
    float* Qs   = sm;                          // [QT][LD]
    float* Ks   = sm + QT * LD;                // [KT2][LD]
    float* Vs   = Ks + KT2 * LD;               // [KT2][LDV]
    float* mskf = Vs + KT2 * LDV;              // [KT2] additive 0 / -1e30

    const int tid = threadIdx.x;
    const int qt  = blockIdx.x;
    const int h   = blockIdx.y;
    const int b   = blockIdx.z;
    const int q0  = qt * QT;

    const int lane = tid & 31;
    const int gid  = lane >> 2;
    const int tig  = lane & 3;
    const int row0 = (tid >> 5) * 16 + gid;

    const float* Qg = g_Q + ((size_t)(b * Hn + h) * Sn + q0) * DKn;
    const float* Kg = g_K + (size_t)(b * Hn + h) * Sn * DKn;
    const float* Vg = g_V + (size_t)(b * Hn + h) * Sn * DKn;

    // Q tile raw copy (already tf32 + scaled)
    {
        const int r   = tid >> 1;
        const int c32 = (tid & 1) * 32;
        #pragma unroll
        for (int u = 0; u < 32; u += 4)
            *(float4*)&Qs[r * LD + c32 + u] = *(const float4*)&Qg[r * DKn + c32 + u];
    }

    float m0 = -1e30f, m1 = -1e30f, l0 = 0.f, l1 = 0.f;
    float o[8][4];
    #pragma unroll
    for (int nt = 0; nt < 8; nt++)
        #pragma unroll
        for (int r = 0; r < 4; r++) o[nt][r] = 0.f;

    for (int kt = 0; kt < Sn / KT2; kt++) {
        const int kk0 = kt * KT2;

        // Stage 128 keys of K and V (raw float4), mask -> additive floats
        {
            const int r   = tid >> 1;            // 0..127
            const int c32 = (tid & 1) * 32;
            #pragma unroll
            for (int u = 0; u < 32; u += 4)
                *(float4*)&Ks[r * LD + c32 + u] =
                    *(const float4*)&Kg[(size_t)(kk0 + r) * DKn + c32 + u];
            #pragma unroll
            for (int u = 0; u < 32; u += 4)
                *(float4*)&Vs[r * LDV + c32 + u] =
                    *(const float4*)&Vg[(size_t)(kk0 + r) * DKn + c32 + u];
        }
        if (tid < KT2) mskf[tid] = (mask[b * Sn + kk0 + tid] == 0) ? -1e30f : 0.f;
        __syncthreads();

        #pragma unroll
        for (int half = 0; half < 2; half++) {
            const float* Kh = Ks + half * 64 * LD;
            const float* Vh = Vs + half * 64 * LDV;
            const float* mh = mskf + half * 64;

            // S = Q @ K^T
            float s[8][4];
            #pragma unroll
            for (int nt = 0; nt < 8; nt++)
                #pragma unroll
                for (int r = 0; r < 4; r++) s[nt][r] = 0.f;

            #pragma unroll
            for (int ks = 0; ks < 8; ks++) {
                const int kk = ks * 8;
                uint32_t a[4];
                const float* Ap = &Qs[row0 * LD + kk + tig];
                a[0] = __float_as_uint(Ap[0]);
                a[1] = __float_as_uint(Ap[8 * LD]);
                a[2] = __float_as_uint(Ap[4]);
                a[3] = __float_as_uint(Ap[8 * LD + 4]);
                #pragma unroll
                for (int nt = 0; nt < 8; nt++) {
                    uint32_t bb[2];
                    const float* Bp = &Kh[(nt * 8 + gid) * LD + kk + tig];
                    bb[0] = __float_as_uint(Bp[0]);
                    bb[1] = __float_as_uint(Bp[4]);
                    MMA_TF32(s[nt], a, bb);
                }
            }

            // Additive mask + in-register online softmax
            float mx0 = -1e30f, mx1 = -1e30f;
            #pragma unroll
            for (int nt = 0; nt < 8; nt++) {
                const float2 mv = *(const float2*)&mh[nt * 8 + tig * 2];
                s[nt][0] += mv.x; s[nt][1] += mv.y;
                s[nt][2] += mv.x; s[nt][3] += mv.y;
                mx0 = fmaxf(mx0, fmaxf(s[nt][0], s[nt][1]));
                mx1 = fmaxf(mx1, fmaxf(s[nt][2], s[nt][3]));
            }
            mx0 = fmaxf(mx0, __shfl_xor_sync(0xffffffffu, mx0, 1));
            mx0 = fmaxf(mx0, __shfl_xor_sync(0xffffffffu, mx0, 2));
            mx1 = fmaxf(mx1, __shfl_xor_sync(0xffffffffu, mx1, 1));
            mx1 = fmaxf(mx1, __shfl_xor_sync(0xffffffffu, mx1, 2));

            const float mn0 = fmaxf(m0, mx0);
            const float mn1 = fmaxf(m1, mx1);
            const float f0  = __expf(m0 - mn0);
            const float f1  = __expf(m1 - mn1);
            m0 = mn0; m1 = mn1;

            float sum0 = 0.f, sum1 = 0.f;
            #pragma unroll
            for (int nt = 0; nt < 8; nt++) {
                float p0 = (s[nt][0] <= -1e29f) ? 0.f : tf32r(__expf(s[nt][0] - mn0));
                float p1 = (s[nt][1] <= -1e29f) ? 0.f : tf32r(__expf(s[nt][1] - mn0));
                float p2 = (s[nt][2] <= -1e29f) ? 0.f : tf32r(__expf(s[nt][2] - mn1));
                float p3 = (s[nt][3] <= -1e29f) ? 0.f : tf32r(__expf(s[nt][3] - mn1));
                s[nt][0] = p0; s[nt][1] = p1; s[nt][2] = p2; s[nt][3] = p3;
                sum0 += p0 + p1;
                sum1 += p2 + p3;
            }
            sum0 += __shfl_xor_sync(0xffffffffu, sum0, 1);
            sum0 += __shfl_xor_sync(0xffffffffu, sum0, 2);
            sum1 += __shfl_xor_sync(0xffffffffu, sum1, 1);
            sum1 += __shfl_xor_sync(0xffffffffu, sum1, 2);
            l0 = l0 * f0 + sum0;
            l1 = l1 * f1 + sum1;

            // Rescale O
            #pragma unroll
            for (int nt = 0; nt < 8; nt++) {
                o[nt][0] *= f0; o[nt][1] *= f0;
                o[nt][2] *= f1; o[nt][3] *= f1;
            }

            // O += P @ V (P C-frag -> A-frag via shuffles)
            {
                const int srcA = (lane & ~3) | (tig >> 1);
                const int srcB = srcA + 2;
                const bool odd = (tig & 1) != 0;
                #pragma unroll
                for (int ks = 0; ks < 8; ks++) {
                    const float v00 = __shfl_sync(0xffffffffu, s[ks][0], srcA);
                    const float v01 = __shfl_sync(0xffffffffu, s[ks][1], srcA);
                    const float v02 = __shfl_sync(0xffffffffu, s[ks][2], srcA);
                    const float v03 = __shfl_sync(0xffffffffu, s[ks][3], srcA);
                    const float v10 = __shfl_sync(0xffffffffu, s[ks][0], srcB);
                    const float v11 = __shfl_sync(0xffffffffu, s[ks][1], srcB);
                    const float v12 = __shfl_sync(0xffffffffu, s[ks][2], srcB);
                    const float v13 = __shfl_sync(0xffffffffu, s[ks][3], srcB);
                    uint32_t a[4];
                    a[0] = __float_as_uint(odd ? v01 : v00);
                    a[1] = __float_as_uint(odd ? v03 : v02);
                    a[2] = __float_as_uint(odd ? v11 : v10);
                    a[3] = __float_as_uint(odd ? v13 : v12);

                    const int kk = ks * 8;
                    #pragma unroll
                    for (int nt = 0; nt < 8; nt++) {
                        uint32_t bb[2];
                        const float* Bp = &Vh[(kk + tig) * LDV + nt * 8 + gid];
                        bb[0] = __float_as_uint(Bp[0]);
                        bb[1] = __float_as_uint(Bp[4 * LDV]);
                        MMA_TF32(o[nt], a, bb);
                    }
                }
            }
        }
        __syncthreads();
    }

    // Normalize and write ctx in (B,S,D) layout
    {
        const float inv0 = 1.f / l0;
        const float inv1 = 1.f / l1;
        #pragma unroll
        for (int nt = 0; nt < 8; nt++) {
            const int col = h * DKn + nt * 8 + tig * 2;
            float2 v0 = { o[nt][0] * inv0, o[nt][1] * inv0 };
            float2 v1 = { o[nt][2] * inv1, o[nt][3] * inv1 };
            *(float2*)&g_ctx[(size_t)(b * Sn + q0 + row0) * Dn + col]     = v0;
            *(float2*)&g_ctx[(size_t)(b * Sn + q0 + row0 + 8) * Dn + col] = v1;
        }
    }
}

// ---------------------------------------------------------------------------
extern "C" void kernel_launch(void* const* d_in, const int* in_sizes, int n_in,
                              void* d_out, int out_size)
{
    const float* q    = (const float*)d_in[0];
    const float* k    = (const float*)d_in[1];
    const float* v    = (const float*)d_in[2];
    const int*   mask = (const int*)  d_in[3];
    const float* Wq   = (const float*)d_in[4];
    const float* bq   = (const float*)d_in[5];
    const float* Wk   = (const float*)d_in[6];
    const float* bk   = (const float*)d_in[7];
    const float* Wv   = (const float*)d_in[8];
    const float* bv   = (const float*)d_in[9];
    const float* Wo   = (const float*)d_in[10];
    const float* bo   = (const float*)d_in[11];
    float* out = (float*)d_out;

    const dim3 gq(Dn / 128, Mn / 128, 3);
    gemm_qkv<<<gq, 256>>>(q, k, v, Wq, Wk, Wv, bq, bk, bv);

    const int fsmem = (QT * LD + KT2 * LD + KT2 * LDV + KT2) * (int)sizeof(float); // 107008 B
    (void)cudaFuncSetAttribute(flash_attn, cudaFuncAttributeMaxDynamicSharedMemorySize, fsmem);
    const dim3 ga(Sn / QT, Hn, Bn);
    flash_attn<<<ga, 256, fsmem>>>(mask);

    const dim3 gg(Dn / 128, Mn / 128);
    gemm_out<<<gg, 256>>>(Wo, bo, out);
}

// round 17
// speedup vs baseline: 1.3325x; 1.1344x over previous
#include <cuda_runtime.h>
#include <math.h>
#include <stdint.h>

#define Bn 4
#define Sn 2048
#define Dn 1024
#define Hn 16
#define DKn 64
#define Mn (Bn*Sn)   /* 8192 */
#define LD 68        /* flash smem row stride: Q/K tiles */
#define LDV 72       /* flash smem row stride: V tile */
#define QT 128       /* q-tile rows per CTA */

// Scratch (device globals: allocation-free per harness rules)
// g_Q: [b][h][s][d] tf32-rounded, pre-scaled by 1/sqrt(DK); g_K/g_V: tf32.
__device__ float g_Q[Bn*Hn*Sn*DKn];
__device__ float g_K[Bn*Hn*Sn*DKn];
__device__ float g_V[Bn*Hn*Sn*DKn];
__device__ float g_ctx[Mn*Dn];

__device__ __forceinline__ uint32_t f2tf(float f) {
    uint32_t u;
    asm("cvt.rna.tf32.f32 %0, %1;" : "=r"(u) : "f"(f));
    return u;
}
__device__ __forceinline__ float tf32r(float f) { return __uint_as_float(f2tf(f)); }

#define MMA_TF32(c, a, b) asm volatile( \
    "mma.sync.aligned.m16n8k8.row.col.f32.tf32.tf32.f32 " \
    "{%0,%1,%2,%3}, {%4,%5,%6,%7}, {%8,%9}, {%0,%1,%2,%3};\n" \
    : "+f"((c)[0]), "+f"((c)[1]), "+f"((c)[2]), "+f"((c)[3]) \
    : "r"((a)[0]), "r"((a)[1]), "r"((a)[2]), "r"((a)[3]), \
      "r"((b)[0]), "r"((b)[1]))

// ---------------------------------------------------------------------------
// tf32 tensor-core GEMM core (R8/R11-proven): double-buffered, XOR-swizzled
// fragment smem. Computes C fragments for a 128x128 tile of A @ W.
// ---------------------------------------------------------------------------
__device__ __forceinline__ void storeAfrag(uint32_t* sA, int arow, int k4, float4 v) {
    const int kt  = k4 >> 3;
    const int reg = (((arow & 15) >= 8) ? 1 : 0) | ((k4 & 4) ? 2 : 0);
    const int a7  = arow & 7;
    const int swz = ((a7 >> 1) & 3) << 2;
    const int base = (((arow >> 4) * 2 + kt) << 7) + (a7 << 4) + reg;
    sA[(base + 0)  ^ swz] = f2tf(v.x);
    sA[(base + 4)  ^ swz] = f2tf(v.y);
    sA[(base + 8)  ^ swz] = f2tf(v.z);
    sA[(base + 12) ^ swz] = f2tf(v.w);
}

__device__ __forceinline__ void storeBfrag(uint32_t* sB, int krow, int n4, float4 v) {
    const int kt    = krow >> 3;
    const int reg   = ((krow & 7) >= 4) ? 1 : 0;
    const int ntile = (n4 >> 3) * 2 + kt;
    const int swz   = ((ntile & 3) << 1) | (((ntile >> 2) & 3) << 3);
    const int base  = ntile * 64 + (n4 & 7) * 8 + (krow & 3) * 2 + reg;
    sB[(base + 0)  ^ swz] = f2tf(v.x);
    sB[(base + 8)  ^ swz] = f2tf(v.y);
    sB[(base + 16) ^ swz] = f2tf(v.z);
    sB[(base + 24) ^ swz] = f2tf(v.w);
}

__device__ __forceinline__ void gemm_body(
    const float* __restrict__ A, const float* __restrict__ W,
    float c[2][8][4], uint32_t (*sA)[2048], uint32_t (*sB)[2048],
    int bx, int by)
{
    const int tid  = threadIdx.x;
    const int wid  = tid >> 5;
    const int lane = tid & 31;
    const int wm   = wid & 3;
    const int wn   = wid >> 2;
    const int la   = (lane << 2) ^ (((lane >> 3) & 3) << 2);

    #pragma unroll
    for (int mt = 0; mt < 2; mt++)
        #pragma unroll
        for (int nt = 0; nt < 8; nt++)
            #pragma unroll
            for (int r = 0; r < 4; r++) c[mt][nt][r] = 0.f;

    const int arow  = tid >> 1;
    const int acol8 = (tid & 1) * 8;
    const int brow  = tid >> 4;
    const int bcol8 = (tid & 15) * 8;

    const float* Ap = A + (size_t)(by * 128 + arow) * Dn + acol8;
    const float* Wp = W + (size_t)brow * Dn + bx * 128 + bcol8;

    float4 ar0 = *(const float4*)Ap;
    float4 ar1 = *(const float4*)(Ap + 4);
    float4 wr0 = *(const float4*)Wp;
    float4 wr1 = *(const float4*)(Wp + 4);
    Ap += 16; Wp += (size_t)16 * Dn;

    storeAfrag(sA[0], arow, acol8,     ar0);
    storeAfrag(sA[0], arow, acol8 + 4, ar1);
    storeBfrag(sB[0], brow, bcol8,     wr0);
    storeBfrag(sB[0], brow, bcol8 + 4, wr1);
    __syncthreads();

    const int NIT = Dn / 16;
    for (int it = 0; it < NIT; it++) {
        const int  p    = it & 1;
        const bool more = (it + 1 < NIT);
        if (more) {
            ar0 = *(const float4*)Ap;
            ar1 = *(const float4*)(Ap + 4);
            wr0 = *(const float4*)Wp;
            wr1 = *(const float4*)(Wp + 4);
            Ap += 16; Wp += (size_t)16 * Dn;
        }

        #pragma unroll
        for (int kt = 0; kt < 2; kt++) {
            uint32_t af[2][4];
            uint32_t bf[8][2];
            #pragma unroll
            for (int mt = 0; mt < 2; mt++)
                *(uint4*)af[mt] =
                    *(const uint4*)&sA[p][(((wm * 2 + mt) * 2 + kt) << 7) + la];
            #pragma unroll
            for (int nt = 0; nt < 8; nt++) {
                const int ntile = (wn * 8 + nt) * 2 + kt;
                const int swz   = ((ntile & 3) << 1) | (((ntile >> 2) & 3) << 3);
                *(uint2*)bf[nt] =
                    *(const uint2*)&sB[p][ntile * 64 + ((lane << 1) ^ swz)];
            }
            #pragma unroll
            for (int mt = 0; mt < 2; mt++)
                #pragma unroll
                for (int nt = 0; nt < 8; nt++)
                    MMA_TF32(c[mt][nt], af[mt], bf[nt]);
        }

        if (more) {
            storeAfrag(sA[p ^ 1], arow, acol8,     ar0);
            storeAfrag(sA[p ^ 1], arow, acol8 + 4, ar1);
            storeBfrag(sB[p ^ 1], brow, bcol8,     wr0);
            storeBfrag(sB[p ^ 1], brow, bcol8 + 4, wr1);
            __syncthreads();
        }
    }
}

// ---------------------------------------------------------------------------
// Fused Q/K/V projection GEMMs (grid.z selects; measured at parity-or-better
// vs separate launches). Head-split row-major [b][h][s][d], tf32-rounded;
// Q additionally pre-scaled by 0.125.
// ---------------------------------------------------------------------------
__global__ __launch_bounds__(256) void gemm_qkv(
    const float* __restrict__ q, const float* __restrict__ k,
    const float* __restrict__ v,
    const float* __restrict__ Wq, const float* __restrict__ Wk,
    const float* __restrict__ Wv,
    const float* __restrict__ bq, const float* __restrict__ bk,
    const float* __restrict__ bv)
{
    __shared__ uint32_t sA[2][2048];
    __shared__ uint32_t sB[2][2048];

    const int dst = blockIdx.z;
    const float* A    = (dst == 0) ? q  : (dst == 1) ? k  : v;
    const float* W    = (dst == 0) ? Wq : (dst == 1) ? Wk : Wv;
    const float* bias = (dst == 0) ? bq : (dst == 1) ? bk : bv;
    float* Out        = (dst == 0) ? g_Q : (dst == 1) ? g_K : g_V;
    const float scl   = (dst == 0) ? 0.125f : 1.0f;

    float c[2][8][4];
    gemm_body(A, W, c, sA, sB, blockIdx.x, blockIdx.y);

    const int lane = threadIdx.x & 31;
    const int wid  = threadIdx.x >> 5;
    const int wm   = wid & 3;
    const int wn   = wid >> 2;
    const int gid  = lane >> 2;
    const int tig  = lane & 3;

    #pragma unroll
    for (int mt = 0; mt < 2; mt++) {
        const int m0 = blockIdx.y * 128 + wm * 32 + mt * 16 + gid;
        const int m1 = m0 + 8;
        const int b0i = m0 >> 11, s0 = m0 & (Sn - 1);
        const int b1i = m1 >> 11, s1 = m1 & (Sn - 1);
        #pragma unroll
        for (int nt = 0; nt < 8; nt++) {
            const int n = blockIdx.x * 128 + wn * 64 + nt * 8 + tig * 2;
            const int h  = n >> 6;
            const int dk = n & 63;
            float2 v0 = { tf32r((c[mt][nt][0] + bias[n])     * scl),
                          tf32r((c[mt][nt][1] + bias[n + 1]) * scl) };
            float2 v1 = { tf32r((c[mt][nt][2] + bias[n])     * scl),
                          tf32r((c[mt][nt][3] + bias[n + 1]) * scl) };
            *(float2*)&Out[((size_t)(b0i * Hn + h) * Sn + s0) * DKn + dk] = v0;
            *(float2*)&Out[((size_t)(b1i * Hn + h) * Sn + s1) * DKn + dk] = v1;
        }
    }
}

// Output projection: out = g_ctx @ Wo + bo (plain fp32 epilogue)
__global__ __launch_bounds__(256) void gemm_out(
    const float* __restrict__ Wo, const float* __restrict__ bo,
    float* __restrict__ out)
{
    __shared__ uint32_t sA[2][2048];
    __shared__ uint32_t sB[2][2048];

    float c[2][8][4];
    gemm_body((const float*)g_ctx, Wo, c, sA, sB, blockIdx.x, blockIdx.y);

    const int lane = threadIdx.x & 31;
    const int wid  = threadIdx.x >> 5;
    const int wm   = wid & 3;
    const int wn   = wid >> 2;
    const int gid  = lane >> 2;
    const int tig  = lane & 3;

    #pragma unroll
    for (int mt = 0; mt < 2; mt++) {
        const int m0 = blockIdx.y * 128 + wm * 32 + mt * 16 + gid;
        #pragma unroll
        for (int nt = 0; nt < 8; nt++) {
            const int n = blockIdx.x * 128 + wn * 64 + nt * 8 + tig * 2;
            float2 v0 = { c[mt][nt][0] + bo[n], c[mt][nt][1] + bo[n + 1] };
            float2 v1 = { c[mt][nt][2] + bo[n], c[mt][nt][3] + bo[n + 1] };
            *(float2*)&out[(size_t)m0 * Dn + n]       = v0;
            *(float2*)&out[(size_t)(m0 + 8) * Dn + n] = v1;
        }
    }
}

// ---------------------------------------------------------------------------
// FA2-style flash attention — R11-exact structure (measured 830us x3):
// 64-key smem tiles, 2 barriers/tile, 70.9KB smem, register-resident S/P,
// in-register online softmax, P->A-frag via shuffles. Staging K/V loads
// merged into one loop (better LDG batching); additive mask (bit-identical).
// ---------------------------------------------------------------------------
__global__ __launch_bounds__(256, 2) void flash_attn(const int* __restrict__ mask)
{
    extern __shared__ float sm[];
    float* Qs   = sm;                        // [QT][LD]  Q (tf32 bits, scaled)
    float* Ks   = sm + QT * LD;              // [64][LD]  K
    float* Vs   = sm + QT * LD + 64 * LD;    // [64][LDV] V
    float* mskf = Vs + 64 * LDV;             // [64] additive 0 / -1e30

    const int tid = threadIdx.x;
    const int qt  = blockIdx.x;
    const int h   = blockIdx.y;
    const int b   = blockIdx.z;
    const int q0  = qt * QT;

    const int lane = tid & 31;
    const int gid  = lane >> 2;
    const int tig  = lane & 3;
    const int row0 = (tid >> 5) * 16 + gid;

    const float* Qg = g_Q + ((size_t)(b * Hn + h) * Sn + q0) * DKn;
    const float* Kg = g_K + (size_t)(b * Hn + h) * Sn * DKn;
    const float* Vg = g_V + (size_t)(b * Hn + h) * Sn * DKn;

    // Q tile raw copy (already tf32 + scaled); each thread one half-row
    {
        const int r   = tid >> 1;
        const int c32 = (tid & 1) * 32;
        #pragma unroll
        for (int u = 0; u < 32; u += 4)
            *(float4*)&Qs[r * LD + c32 + u] = *(const float4*)&Qg[r * DKn + c32 + u];
    }

    float m0 = -1e30f, m1 = -1e30f, l0 = 0.f, l1 = 0.f;
    float o[8][4];
    #pragma unroll
    for (int nt = 0; nt < 8; nt++)
        #pragma unroll
        for (int r = 0; r < 4; r++) o[nt][r] = 0.f;

    for (int kt = 0; kt < Sn / 64; kt++) {
        const int kk0 = kt * 64;

        // K and V tiles: merged loop so all 8 LDG.128 batch before STS
        {
            const int r  = tid >> 2;
            const int c4 = (tid & 3) * 16;
            const float* kp = &Kg[(size_t)(kk0 + r) * DKn + c4];
            const float* vp = &Vg[(size_t)(kk0 + r) * DKn + c4];
            #pragma unroll
            for (int u = 0; u < 16; u += 4) {
                float4 kv = *(const float4*)(kp + u);
                float4 vv = *(const float4*)(vp + u);
                *(float4*)&Ks[r * LD + c4 + u]  = kv;
                *(float4*)&Vs[r * LDV + c4 + u] = vv;
            }
        }
        if (tid < 64) mskf[tid] = (mask[b * Sn + kk0 + tid] == 0) ? -1e30f : 0.f;
        __syncthreads();

        // S = Q @ K^T : warp computes its 16 rows x 64 cols (8 n-tiles)
        float s[8][4];
        #pragma unroll
        for (int nt = 0; nt < 8; nt++)
            #pragma unroll
            for (int r = 0; r < 4; r++) s[nt][r] = 0.f;

        #pragma unroll
        for (int ks = 0; ks < 8; ks++) {
            const int kk = ks * 8;
            uint32_t a[4];
            const float* Ap = &Qs[row0 * LD + kk + tig];
            a[0] = __float_as_uint(Ap[0]);
            a[1] = __float_as_uint(Ap[8 * LD]);
            a[2] = __float_as_uint(Ap[4]);
            a[3] = __float_as_uint(Ap[8 * LD + 4]);
            #pragma unroll
            for (int nt = 0; nt < 8; nt++) {
                uint32_t bb[2];
                const float* Bp = &Ks[(nt * 8 + gid) * LD + kk + tig];
                bb[0] = __float_as_uint(Bp[0]);
                bb[1] = __float_as_uint(Bp[4]);
                MMA_TF32(s[nt], a, bb);
            }
        }

        // Additive mask + in-register online softmax
        float mx0 = -1e30f, mx1 = -1e30f;
        #pragma unroll
        for (int nt = 0; nt < 8; nt++) {
            const float2 mv = *(const float2*)&mskf[nt * 8 + tig * 2];
            s[nt][0] += mv.x; s[nt][1] += mv.y;
            s[nt][2] += mv.x; s[nt][3] += mv.y;
            mx0 = fmaxf(mx0, fmaxf(s[nt][0], s[nt][1]));
            mx1 = fmaxf(mx1, fmaxf(s[nt][2], s[nt][3]));
        }
        mx0 = fmaxf(mx0, __shfl_xor_sync(0xffffffffu, mx0, 1));
        mx0 = fmaxf(mx0, __shfl_xor_sync(0xffffffffu, mx0, 2));
        mx1 = fmaxf(mx1, __shfl_xor_sync(0xffffffffu, mx1, 1));
        mx1 = fmaxf(mx1, __shfl_xor_sync(0xffffffffu, mx1, 2));

        const float mn0 = fmaxf(m0, mx0);
        const float mn1 = fmaxf(m1, mx1);
        const float f0  = __expf(m0 - mn0);
        const float f1  = __expf(m1 - mn1);
        m0 = mn0; m1 = mn1;

        float sum0 = 0.f, sum1 = 0.f;
        #pragma unroll
        for (int nt = 0; nt < 8; nt++) {
            float p0 = (s[nt][0] <= -1e29f) ? 0.f : tf32r(__expf(s[nt][0] - mn0));
            float p1 = (s[nt][1] <= -1e29f) ? 0.f : tf32r(__expf(s[nt][1] - mn0));
            float p2 = (s[nt][2] <= -1e29f) ? 0.f : tf32r(__expf(s[nt][2] - mn1));
            float p3 = (s[nt][3] <= -1e29f) ? 0.f : tf32r(__expf(s[nt][3] - mn1));
            s[nt][0] = p0; s[nt][1] = p1; s[nt][2] = p2; s[nt][3] = p3;
            sum0 += p0 + p1;
            sum1 += p2 + p3;
        }
        sum0 += __shfl_xor_sync(0xffffffffu, sum0, 1);
        sum0 += __shfl_xor_sync(0xffffffffu, sum0, 2);
        sum1 += __shfl_xor_sync(0xffffffffu, sum1, 1);
        sum1 += __shfl_xor_sync(0xffffffffu, sum1, 2);
        l0 = l0 * f0 + sum0;
        l1 = l1 * f1 + sum1;

        // Rescale O
        #pragma unroll
        for (int nt = 0; nt < 8; nt++) {
            o[nt][0] *= f0; o[nt][1] *= f0;
            o[nt][2] *= f1; o[nt][3] *= f1;
        }

        // O += P @ V (P C-frag -> A-frag via shuffles)
        {
            const int srcA = (lane & ~3) | (tig >> 1);
            const int srcB = srcA + 2;
            const bool odd = (tig & 1) != 0;
            #pragma unroll
            for (int ks = 0; ks < 8; ks++) {
                const float v00 = __shfl_sync(0xffffffffu, s[ks][0], srcA);
                const float v01 = __shfl_sync(0xffffffffu, s[ks][1], srcA);
                const float v02 = __shfl_sync(0xffffffffu, s[ks][2], srcA);
                const float v03 = __shfl_sync(0xffffffffu, s[ks][3], srcA);
                const float v10 = __shfl_sync(0xffffffffu, s[ks][0], srcB);
                const float v11 = __shfl_sync(0xffffffffu, s[ks][1], srcB);
                const float v12 = __shfl_sync(0xffffffffu, s[ks][2], srcB);
                const float v13 = __shfl_sync(0xffffffffu, s[ks][3], srcB);
                uint32_t a[4];
                a[0] = __float_as_uint(odd ? v01 : v00);   // P[gid   ][kk+tig]
                a[1] = __float_as_uint(odd ? v03 : v02);   // P[gid+8 ][kk+tig]
                a[2] = __float_as_uint(odd ? v11 : v10);   // P[gid   ][kk+tig+4]
                a[3] = __float_as_uint(odd ? v13 : v12);   // P[gid+8 ][kk+tig+4]

                const int kk = ks * 8;
                #pragma unroll
                for (int nt = 0; nt < 8; nt++) {
                    uint32_t bb[2];
                    const float* Bp = &Vs[(kk + tig) * LDV + nt * 8 + gid];
                    bb[0] = __float_as_uint(Bp[0]);
                    bb[1] = __float_as_uint(Bp[4 * LDV]);
                    MMA_TF32(o[nt], a, bb);
                }
            }
        }
        __syncthreads();
    }

    // Normalize and write ctx in (B,S,D) layout
    {
        const float inv0 = 1.f / l0;
        const float inv1 = 1.f / l1;
        #pragma unroll
        for (int nt = 0; nt < 8; nt++) {
            const int col = h * DKn + nt * 8 + tig * 2;
            float2 v0 = { o[nt][0] * inv0, o[nt][1] * inv0 };
            float2 v1 = { o[nt][2] * inv1, o[nt][3] * inv1 };
            *(float2*)&g_ctx[(size_t)(b * Sn + q0 + row0) * Dn + col]     = v0;
            *(float2*)&g_ctx[(size_t)(b * Sn + q0 + row0 + 8) * Dn + col] = v1;
        }
    }
}

// ---------------------------------------------------------------------------
extern "C" void kernel_launch(void* const* d_in, const int* in_sizes, int n_in,
                              void* d_out, int out_size)
{
    const float* q    = (const float*)d_in[0];
    const float* k    = (const float*)d_in[1];
    const float* v    = (const float*)d_in[2];
    const int*   mask = (const int*)  d_in[3];
    const float* Wq   = (const float*)d_in[4];
    const float* bq   = (const float*)d_in[5];
    const float* Wk   = (const float*)d_in[6];
    const float* bk   = (const float*)d_in[7];
    const float* Wv   = (const float*)d_in[8];
    const float* bv   = (const float*)d_in[9];
    const float* Wo   = (const float*)d_in[10];
    const float* bo   = (const float*)d_in[11];
    float* out = (float*)d_out;

    const dim3 gq(Dn / 128, Mn / 128, 3);
    gemm_qkv<<<gq, 256>>>(q, k, v, Wq, Wk, Wv, bq, bk, bv);

    const int fsmem = (QT * LD + 64 * LD + 64 * LDV + 64) * (int)sizeof(float); // 70912 B
    (void)cudaFuncSetAttribute(flash_attn, cudaFuncAttributeMaxDynamicSharedMemorySize, fsmem);
    const dim3 ga(Sn / QT, Hn, Bn);
    flash_attn<<<ga, 256, fsmem>>>(mask);

    const dim3 gg(Dn / 128, Mn / 128);
    gemm_out<<<gg, 256>>>(Wo, bo, out);
}